// round 8
// baseline (speedup 1.0000x reference)
#include <cuda_runtime.h>
#include <math.h>

#define NLAT 128
#define NLON 256
#define LMAX 50
#define MMAX 50
#define NPTS 2048
#define NB   2
#define MG   (NLAT*NLON)
#define NBT  32
#define NBP  64
#define NBINS (NBT*NBP)
#define PI_F 3.14159265358979323846f
#define H_BIN (PI_F/32.0f)
#define INVH  (32.0f/PI_F)
#define CAP   1536
#define NBLK  512
#define KINF  0x7F7FFFFFu

// ---- device scratch (globals; zero-init at load) ----
__device__ float4 g_sorted[4][NPTS];
__device__ int    g_binstart[4][NBINS + 1];
__device__ float  g_grid[4][MG];
__device__ float  g_pctw[MMAX][LMAX][NLAT];
__device__ float  g_part[NB * LMAX * MMAX];
__device__ int    g_barc[2 * 32];
__device__ int    g_done;

union Smem {
    struct { float4 pts[NPTS]; int cnt[NBINS]; int wsum[8]; } prep;   // ~41KB
    struct { float4 cand[CAP]; int rowoff[12]; int rowsrc[12]; } it;  // ~24KB
    struct { float ctab[NLON]; float px[2][NLAT]; float tx[2][NLAT];
             float xfp[NLAT]; float xft[NLAT];
             float plp[4][64]; float plt[4][64]; } cd;                // ~8KB
    float red[64];
};

__device__ __forceinline__ void gbar(int id) {
    __syncthreads();
    if (threadIdx.x == 0) {
        __threadfence();
        atomicAdd(&g_barc[id * 32], 1);
        while (*(volatile int*)&g_barc[id * 32] < NBLK) __nanosleep(64);
        __threadfence();
        int l = atomicAdd(&g_barc[id * 32 + 1], 1);
        if (l == NBLK - 1) {
            *(volatile int*)&g_barc[id * 32]     = 0;
            *(volatile int*)&g_barc[id * 32 + 1] = 0;
            __threadfence();
        }
    }
    __syncthreads();
}

__device__ __forceinline__ int bin_of(float th, float ph) {
    int bt = (int)(th * INVH);
    int bp = (int)((ph + PI_F) * INVH);
    bt = min(max(bt, 0), NBT - 1);
    bp = min(max(bp, 0), NBP - 1);
    return bt * NBP + bp;
}

__device__ __forceinline__ void ins3(unsigned& k0, unsigned& k1, unsigned& k2, unsigned key) {
    unsigned t  = max(k0, key); k0 = min(k0, key);
    unsigned t2 = max(k1, t);   k1 = min(k1, t);
    k2 = min(k2, t2);
}

__global__ void __launch_bounds__(256, 4)
k_mega(const float* __restrict__ pred, const float* __restrict__ tgt,
       float* __restrict__ out) {
    __shared__ Smem sm;
    __shared__ int s_last;
    int bid  = blockIdx.x;
    int tid  = threadIdx.x;
    int lane = tid & 31;
    int wid  = tid >> 5;

    // ================= Phase A: prep (blocks 0-3) + pctw (4-28) =============
    if (bid < 4) {
        int cb = bid;
        int t = cb >> 1, b = cb & 1;
        const float* src = (t ? tgt : pred) + (size_t)b * NPTS * 3;
        for (int i = tid; i < NBINS; i += 256) sm.prep.cnt[i] = 0;
        __syncthreads();
        for (int i = tid; i < NPTS; i += 256) {
            float x = src[3 * i], y = src[3 * i + 1], z = src[3 * i + 2];
            float r   = sqrtf(x * x + y * y + z * z);
            float pn1 = sqrtf(y * y + z * z);
            float th  = acosf(fminf(fmaxf(x / r,   -1.0f), 1.0f));
            float a   = acosf(fminf(fmaxf(y / pn1, -1.0f), 1.0f));
            float ph  = ((z < 0.0f) ? (2.0f * PI_F - a) : a) - PI_F;
            float4 o; o.x = th; o.y = ph; o.z = r; o.w = 0.0f;
            sm.prep.pts[i] = o;
            atomicAdd(&sm.prep.cnt[bin_of(th, ph)], 1);
        }
        __syncthreads();
        int base = tid * 8;
        int local[8]; int s = 0;
#pragma unroll
        for (int j = 0; j < 8; ++j) { local[j] = s; s += sm.prep.cnt[base + j]; }
        int v = s;
#pragma unroll
        for (int o = 1; o < 32; o <<= 1) {
            int u = __shfl_up_sync(0xffffffffu, v, o);
            if (lane >= o) v += u;
        }
        if (lane == 31) sm.prep.wsum[wid] = v;
        __syncthreads();
        if (tid == 0) {
            int a = 0;
            for (int j = 0; j < 8; ++j) { int x = sm.prep.wsum[j]; sm.prep.wsum[j] = a; a += x; }
        }
        __syncthreads();
        int excl = v - s + sm.prep.wsum[wid];
#pragma unroll
        for (int j = 0; j < 8; ++j) {
            int off = excl + local[j];
            sm.prep.cnt[base + j] = off;
            g_binstart[cb][base + j] = off;
        }
        if (tid == 0) g_binstart[cb][NBINS] = NPTS;
        __syncthreads();
        for (int i = tid; i < NPTS; i += 256) {
            float4 p = sm.prep.pts[i];
            int pos = atomicAdd(&sm.prep.cnt[bin_of(p.x, p.y)], 1);
            g_sorted[cb][pos] = p;
        }
    } else if (bid < 29) {
        int m = (bid - 4) * 2 + (tid >> 7);
        int k = tid & 127;
        if (m < MMAX) {
            float theta = PI_F * (float)k / (float)(NLAT - 1);
            float cost  = cosf(theta);
            float sint  = sqrtf(fmaxf(1.0f - cost * cost, 0.0f));
            // Clenshaw-Curtis weight via Chebyshev recurrence on cos(2j*theta)
            float c2  = cosf(2.0f * theta);
            float tc2 = 2.0f * c2;
            float cm1 = 1.0f, cj = c2;
            float v = 0.0f;
#pragma unroll 7
            for (int j = 1; j <= 63; ++j) {
                v = fmaf(cj, 2.0f / (4.0f * (float)j * (float)j - 1.0f), v);
                float cn = fmaf(tc2, cj, -cm1);
                cm1 = cj; cj = cn;
            }
            float w = (2.0f / 127.0f) * (1.0f - v);
            if (k == 0 || k == 127) w *= 0.5f;
            float pmm = sqrtf(1.0f / (4.0f * PI_F));
            for (int mm = 1; mm <= m; ++mm)
                pmm = -pmm * sqrtf((2.0f * mm + 1.0f) / (2.0f * mm)) * sint;
            for (int l = 0; l < m; ++l) g_pctw[m][l][k] = 0.0f;
            g_pctw[m][m][k] = pmm * w;
            if (m + 1 < LMAX) {
                float plm2 = pmm;
                float plm1 = sqrtf(2.0f * m + 3.0f) * cost * pmm;
                g_pctw[m][m + 1][k] = plm1 * w;
                for (int l = m + 2; l < LMAX; ++l) {
                    float fl = (float)l, fm = (float)m;
                    float a = sqrtf((4.0f * fl * fl - 1.0f) / (fl * fl - fm * fm));
                    float bq = sqrtf(((2.0f * fl + 1.0f) * (fl - 1.0f + fm) * (fl - 1.0f - fm)) /
                                     ((2.0f * fl - 3.0f) * (fl * fl - fm * fm)));
                    float pl = a * cost * plm1 - bq * plm2;
                    g_pctw[m][l][k] = pl * w;
                    plm2 = plm1; plm1 = pl;
                }
            }
        }
    }
    gbar(0);

    // ================= Phase B: 3-NN interp (512 tiles) =====================
    {
        int cb  = bid >> 7;
        int rem = bid & 127;
        int ty8 = rem >> 4, tx16 = rem & 15;
        int bt0 = ty8 * 4, bp0 = tx16 * 4;
        bool pole = (ty8 == 0) || (ty8 == 7);

        int irow = ty8 * 16 + (tid >> 4);
        int icol = tx16 * 16 + (tid & 15);
        float gth = (float)irow * (PI_F / NLAT);
        float gph = (float)(icol - NLAT) * (PI_F / NLAT);

        int ncand;
        float margin;
        int sk_t0, sk_t1, sk_p0, sk_p1;

        if (pole) {
            int r0 = (ty8 == 0) ? 0 : 25;
            int r1 = (ty8 == 0) ? 6 : 31;
            if (tid == 0) {
                sm.it.rowsrc[0] = g_binstart[cb][r0 * NBP];
                sm.it.rowoff[0] = g_binstart[cb][(r1 + 1) * NBP];
            }
            __syncthreads();
            int s0 = sm.it.rowsrc[0], e0 = sm.it.rowoff[0];
            ncand = e0 - s0;
            if (ncand <= CAP) {
                for (int i = tid; i < ncand; i += 256) {
                    float4 p = g_sorted[cb][s0 + i];
                    p.w = __uint_as_float((unsigned)(s0 + i));
                    sm.it.cand[i] = p;
                }
            }
            margin = (ty8 == 0) ? (7.0f * H_BIN - gth) : (gth - 25.0f * H_BIN);
            sk_t0 = r0; sk_t1 = r1; sk_p0 = 0; sk_p1 = NBP - 1;
        } else {
            int ht0 = max(bt0 - 2, 0), ht1 = min(bt0 + 5, NBT - 1);
            int hp0 = max(bp0 - 2, 0), hp1 = min(bp0 + 5, NBP - 1);
            int nrows = ht1 - ht0 + 1;
            if (tid < nrows) {
                int s = g_binstart[cb][(ht0 + tid) * NBP + hp0];
                int e = g_binstart[cb][(ht0 + tid) * NBP + hp1 + 1];
                sm.it.rowsrc[tid] = s;
                sm.it.rowoff[tid] = e - s;
            }
            __syncthreads();
            if (tid == 0) {
                int off = 0;
                for (int r = 0; r < nrows; ++r) {
                    int len = sm.it.rowoff[r];
                    sm.it.rowoff[r] = off;
                    off += len;
                }
                sm.it.rowoff[nrows] = off;
            }
            __syncthreads();
            ncand = sm.it.rowoff[nrows];
            if (ncand <= CAP) {
                for (int r = 0; r < nrows; ++r) {
                    int o0 = sm.it.rowoff[r], len = sm.it.rowoff[r + 1] - o0, s0 = sm.it.rowsrc[r];
                    for (int i = tid; i < len; i += 256) {
                        float4 p = g_sorted[cb][s0 + i];
                        p.w = __uint_as_float((unsigned)(s0 + i));
                        sm.it.cand[o0 + i] = p;
                    }
                }
            }
            float mT = (ht0 > 0)       ? (gth - (float)ht0 * H_BIN)       : 1e9f;
            float mB = (ht1 < NBT - 1) ? ((float)(ht1 + 1) * H_BIN - gth) : 1e9f;
            float gpp = gph + PI_F;
            float mL = (hp0 > 0)       ? (gpp - (float)hp0 * H_BIN)       : 1e9f;
            float mR = (hp1 < NBP - 1) ? ((float)(hp1 + 1) * H_BIN - gpp) : 1e9f;
            margin = fminf(fminf(mT, mB), fminf(mL, mR));
            sk_t0 = ht0; sk_t1 = ht1; sk_p0 = hp0; sk_p1 = hp1;
        }
        __syncthreads();

        bool ovf = ncand > CAP;
        unsigned k0 = KINF, k1 = KINF, k2 = KINF;

        if (!ovf) {
#pragma unroll 4
            for (int i = 0; i < ncand; ++i) {
                float4 p = sm.it.cand[i];
                float dx = gth - p.x, dy = gph - p.y;
                float d = fmaf(dx, dx, dy * dy);
                unsigned key = (__float_as_uint(d) & 0xFFFFF800u) | __float_as_uint(p.w);
                ins3(k0, k1, k2, key);
            }
        }

        float d2k = __uint_as_float(k2 & 0xFFFFF800u);
        if (ovf || d2k > margin * margin) {
            int bt = min(irow >> 2, NBT - 1);
            int bp = min(icol >> 2, NBP - 1);
            int st0 = ovf ? 1000 : sk_t0, st1 = ovf ? -1 : sk_t1;
            int sp0 = ovf ? 1000 : sk_p0, sp1 = ovf ? -1 : sk_p1;
            for (int R = 0; R <= 64; ++R) {
                if (R > 0) {
                    float lb = (float)(R - 1) * H_BIN;
                    d2k = __uint_as_float(k2 & 0xFFFFF800u);
                    if (d2k <= lb * lb) break;
                }
                int t0 = max(bt - R, 0), t1 = min(bt + R, NBT - 1);
                int p0 = max(bp - R, 0), p1 = min(bp + R, NBP - 1);
                for (int y = t0; y <= t1; ++y) {
                    bool full = (R == 0) || (y == bt - R) || (y == bt + R);
                    int xs = full ? p0 : (bp - R);
                    int xe = full ? p1 : (bp + R);
                    int xstep = full ? 1 : (2 * R);
                    for (int x = xs; x <= xe; x += xstep) {
                        if (x < 0 || x > NBP - 1) continue;
                        if (y >= st0 && y <= st1 && x >= sp0 && x <= sp1) continue;
                        int bi = y * NBP + x;
                        int s0 = g_binstart[cb][bi], s1 = g_binstart[cb][bi + 1];
                        for (int i = s0; i < s1; ++i) {
                            float4 p = g_sorted[cb][i];
                            float dx = gth - p.x, dy = gph - p.y;
                            float d = fmaf(dx, dx, dy * dy);
                            unsigned key = (__float_as_uint(d) & 0xFFFFF800u) | (unsigned)i;
                            ins3(k0, k1, k2, key);
                        }
                    }
                }
            }
        }

        float4 q0 = g_sorted[cb][k0 & 0x7FFu];
        float4 q1 = g_sorted[cb][k1 & 0x7FFu];
        float4 q2 = g_sorted[cb][k2 & 0x7FFu];
        float dx, dy;
        dx = gth - q0.x; dy = gph - q0.y; float e0 = fmaf(dx, dx, dy * dy);
        dx = gth - q1.x; dy = gph - q1.y; float e1 = fmaf(dx, dx, dy * dy);
        dx = gth - q2.x; dy = gph - q2.y; float e2 = fmaf(dx, dx, dy * dy);
        float s = e0 + e1 + e2;
        g_grid[cb][irow * NLON + icol] = (e0 * q0.z + e1 * q1.z + e2 * q2.z) / s;
    }
    gbar(1);

    // ================= Phase CD: DFT + Legendre + partial loss ==============
    // block = (batch b, mode m): 100 blocks. Others fall through to done.
    if (bid < NB * MMAX) {
        int b = bid / MMAX;
        int m = bid % MMAX;
        sm.cd.ctab[tid] = cosf((2.0f * PI_F / NLON) * (float)m * (float)tid);
        __syncthreads();

        // xf[k] for pred & target: thread = (k, half)
        {
            int k = tid >> 1, h = tid & 1;
            const float* gp = &g_grid[b][k * NLON + h * 128];
            const float* gt = &g_grid[2 + b][k * NLON + h * 128];
            const float* ct = &sm.cd.ctab[h * 128];
            float ap0 = 0.0f, ap1 = 0.0f, at0 = 0.0f, at1 = 0.0f;
#pragma unroll 8
            for (int i = 0; i < 128; i += 2) {
                float c0 = ct[i], c1 = ct[i + 1];
                ap0 = fmaf(gp[i],     c0, ap0);
                ap1 = fmaf(gp[i + 1], c1, ap1);
                at0 = fmaf(gt[i],     c0, at0);
                at1 = fmaf(gt[i + 1], c1, at1);
            }
            sm.cd.px[h][k] = ap0 + ap1;
            sm.cd.tx[h][k] = at0 + at1;
        }
        __syncthreads();
        if (tid < NLAT) {
            sm.cd.xfp[tid] = (sm.cd.px[0][tid] + sm.cd.px[1][tid]) * (2.0f * PI_F / NLON);
            sm.cd.xft[tid] = (sm.cd.tx[0][tid] + sm.cd.tx[1][tid]) * (2.0f * PI_F / NLON);
        }
        __syncthreads();

        // legendre contraction: thread = (l, quarter)
        {
            int l = tid & 63, q = tid >> 6;
            if (l < LMAX) {
                const float* pw = &g_pctw[m][l][q * 32];
                const float* xp = &sm.cd.xfp[q * 32];
                const float* xt = &sm.cd.xft[q * 32];
                float pc = 0.0f, tc = 0.0f;
#pragma unroll 8
                for (int k = 0; k < 32; ++k) {
                    float w = pw[k];
                    pc = fmaf(xp[k], w, pc);
                    tc = fmaf(xt[k], w, tc);
                }
                sm.cd.plp[q][l] = pc;
                sm.cd.plt[q][l] = tc;
            }
        }
        __syncthreads();
        if (tid < LMAX) {
            int l = tid;
            float pc = (sm.cd.plp[0][l] + sm.cd.plp[1][l]) + (sm.cd.plp[2][l] + sm.cd.plp[3][l]);
            float tc = (sm.cd.plt[0][l] + sm.cd.plt[1][l]) + (sm.cd.plt[2][l] + sm.cd.plt[3][l]);
            float d = pc - tc;
            float q = (float)(LMAX - 1 - l);
            g_part[b * (LMAX * MMAX) + l * MMAX + m] = d * d * expf(-q * q / (2.0f * LMAX * LMAX));
        }
    }

    // ================= Final: last block reduces ============================
    __syncthreads();
    if (tid == 0) {
        __threadfence();
        int t = atomicAdd(&g_done, 1);
        s_last = (t == NBLK - 1) ? 1 : 0;
    }
    __syncthreads();
    if (s_last) {
        __threadfence();
        float acc = 0.0f;
        for (int i = tid; i < NB * LMAX * MMAX; i += 256) acc += g_part[i];
#pragma unroll
        for (int o = 16; o > 0; o >>= 1) acc += __shfl_down_sync(0xffffffffu, acc, o);
        if (lane == 0) sm.red[wid] = acc;
        __syncthreads();
        if (tid == 0) {
            float v = 0.0f;
            for (int j = 0; j < 8; ++j) v += sm.red[j];
            out[0] = v / (float)NB;
            g_done = 0;
            __threadfence();
        }
    }
}

extern "C" void kernel_launch(void* const* d_in, const int* in_sizes, int n_in,
                              void* d_out, int out_size) {
    const float* pred = (const float*)d_in[0];
    const float* tgt  = (const float*)d_in[1];
    k_mega<<<NBLK, 256>>>(pred, tgt, (float*)d_out);
}

// round 10
// speedup vs baseline: 1.0246x; 1.0246x over previous
#include <cuda_runtime.h>
#include <math.h>

#define NLAT 128
#define NLON 256
#define LMAX 50
#define MMAX 50
#define NPTS 2048
#define NB   2
#define MG   (NLAT*NLON)
#define NBT  32
#define NBP  64
#define NBINS (NBT*NBP)
#define PI_F 3.14159265358979323846f
#define H_BIN (PI_F/32.0f)
#define INVH  (32.0f/PI_F)
#define CAP   1536
#define NBLK  512
#define KINF  0x7F7FFFFFu

// ---- device scratch (globals; zero-init at load) ----
__device__ float4 g_sorted[4][NPTS];
__device__ int    g_binstart[4][NBINS + 1];
__device__ float  g_grid[4][MG];
__device__ float  g_pctw[MMAX][LMAX][NLAT];
__device__ float  g_part[NB * LMAX * MMAX];
__device__ int    g_barc[2 * 32];
__device__ int    g_done;

union Smem {
    struct { float4 pts[NPTS]; int cnt[NBINS]; int wsum[8]; } prep;   // ~41KB
    struct { float4 cand[CAP]; int rowoff[12]; int rowsrc[12]; } it;  // ~24KB
    struct { float ctab[NLON]; float xfp[NLAT]; float xft[NLAT];
             float plp[4][64]; float plt[4][64]; } cd;                // ~4KB
    float red[64];
};

__device__ __forceinline__ void gbar(int id) {
    __syncthreads();
    if (threadIdx.x == 0) {
        __threadfence();
        atomicAdd(&g_barc[id * 32], 1);
        while (*(volatile int*)&g_barc[id * 32] < NBLK) __nanosleep(64);
        __threadfence();
        int l = atomicAdd(&g_barc[id * 32 + 1], 1);
        if (l == NBLK - 1) {
            *(volatile int*)&g_barc[id * 32]     = 0;
            *(volatile int*)&g_barc[id * 32 + 1] = 0;
            __threadfence();
        }
    }
    __syncthreads();
}

__device__ __forceinline__ int bin_of(float th, float ph) {
    int bt = (int)(th * INVH);
    int bp = (int)((ph + PI_F) * INVH);
    bt = min(max(bt, 0), NBT - 1);
    bp = min(max(bp, 0), NBP - 1);
    return bt * NBP + bp;
}

__device__ __forceinline__ void ins3(unsigned& k0, unsigned& k1, unsigned& k2, unsigned key) {
    unsigned t  = max(k0, key); k0 = min(k0, key);
    unsigned t2 = max(k1, t);   k1 = min(k1, t);
    k2 = min(k2, t2);
}

__global__ void __launch_bounds__(256, 4)
k_mega(const float* __restrict__ pred, const float* __restrict__ tgt,
       float* __restrict__ out) {
    __shared__ Smem sm;
    __shared__ int s_last;
    int bid  = blockIdx.x;
    int tid  = threadIdx.x;
    int lane = tid & 31;
    int wid  = tid >> 5;

    // ================= Phase A: prep (blocks 0-3) + pctw (4-28) =============
    if (bid < 4) {
        int cb = bid;
        int t = cb >> 1, b = cb & 1;
        const float* src = (t ? tgt : pred) + (size_t)b * NPTS * 3;
        for (int i = tid; i < NBINS; i += 256) sm.prep.cnt[i] = 0;
        __syncthreads();
        for (int i = tid; i < NPTS; i += 256) {
            float x = src[3 * i], y = src[3 * i + 1], z = src[3 * i + 2];
            float r   = sqrtf(x * x + y * y + z * z);
            float pn1 = sqrtf(y * y + z * z);
            float th  = acosf(fminf(fmaxf(x / r,   -1.0f), 1.0f));
            float a   = acosf(fminf(fmaxf(y / pn1, -1.0f), 1.0f));
            float ph  = ((z < 0.0f) ? (2.0f * PI_F - a) : a) - PI_F;
            float4 o; o.x = th; o.y = ph; o.z = r; o.w = 0.0f;
            sm.prep.pts[i] = o;
            atomicAdd(&sm.prep.cnt[bin_of(th, ph)], 1);
        }
        __syncthreads();
        int base = tid * 8;
        int local[8]; int s = 0;
#pragma unroll
        for (int j = 0; j < 8; ++j) { local[j] = s; s += sm.prep.cnt[base + j]; }
        int v = s;
#pragma unroll
        for (int o = 1; o < 32; o <<= 1) {
            int u = __shfl_up_sync(0xffffffffu, v, o);
            if (lane >= o) v += u;
        }
        if (lane == 31) sm.prep.wsum[wid] = v;
        __syncthreads();
        if (tid == 0) {
            int a = 0;
            for (int j = 0; j < 8; ++j) { int x = sm.prep.wsum[j]; sm.prep.wsum[j] = a; a += x; }
        }
        __syncthreads();
        int excl = v - s + sm.prep.wsum[wid];
#pragma unroll
        for (int j = 0; j < 8; ++j) {
            int off = excl + local[j];
            sm.prep.cnt[base + j] = off;
            g_binstart[cb][base + j] = off;
        }
        if (tid == 0) g_binstart[cb][NBINS] = NPTS;
        __syncthreads();
        for (int i = tid; i < NPTS; i += 256) {
            float4 p = sm.prep.pts[i];
            int pos = atomicAdd(&sm.prep.cnt[bin_of(p.x, p.y)], 1);
            g_sorted[cb][pos] = p;
        }
    } else if (bid < 29) {
        int m = (bid - 4) * 2 + (tid >> 7);
        int k = tid & 127;
        if (m < MMAX) {
            float theta = PI_F * (float)k / (float)(NLAT - 1);
            float cost  = cosf(theta);
            float sint  = sqrtf(fmaxf(1.0f - cost * cost, 0.0f));
            float c2  = cosf(2.0f * theta);
            float tc2 = 2.0f * c2;
            float cm1 = 1.0f, cj = c2;
            float v = 0.0f;
#pragma unroll 7
            for (int j = 1; j <= 63; ++j) {
                v = fmaf(cj, 2.0f / (4.0f * (float)j * (float)j - 1.0f), v);
                float cn = fmaf(tc2, cj, -cm1);
                cm1 = cj; cj = cn;
            }
            float w = (2.0f / 127.0f) * (1.0f - v);
            if (k == 0 || k == 127) w *= 0.5f;
            float pmm = sqrtf(1.0f / (4.0f * PI_F));
            for (int mm = 1; mm <= m; ++mm)
                pmm = -pmm * sqrtf((2.0f * mm + 1.0f) / (2.0f * mm)) * sint;
            for (int l = 0; l < m; ++l) g_pctw[m][l][k] = 0.0f;
            g_pctw[m][m][k] = pmm * w;
            if (m + 1 < LMAX) {
                float plm2 = pmm;
                float plm1 = sqrtf(2.0f * m + 3.0f) * cost * pmm;
                g_pctw[m][m + 1][k] = plm1 * w;
                for (int l = m + 2; l < LMAX; ++l) {
                    float fl = (float)l, fm = (float)m;
                    float a = sqrtf((4.0f * fl * fl - 1.0f) / (fl * fl - fm * fm));
                    float bq = sqrtf(((2.0f * fl + 1.0f) * (fl - 1.0f + fm) * (fl - 1.0f - fm)) /
                                     ((2.0f * fl - 3.0f) * (fl * fl - fm * fm)));
                    float pl = a * cost * plm1 - bq * plm2;
                    g_pctw[m][l][k] = pl * w;
                    plm2 = plm1; plm1 = pl;
                }
            }
        }
    }
    gbar(0);

    // ================= Phase B: 3-NN interp (512 tiles) =====================
    {
        int cb  = bid >> 7;
        int rem = bid & 127;
        int ty8 = rem >> 4, tx16 = rem & 15;
        int bt0 = ty8 * 4, bp0 = tx16 * 4;
        bool pole = (ty8 == 0) || (ty8 == 7);

        int irow = ty8 * 16 + (tid >> 4);
        int icol = tx16 * 16 + (tid & 15);
        float gth = (float)irow * (PI_F / NLAT);
        float gph = (float)(icol - NLAT) * (PI_F / NLAT);

        int ncand;
        float margin;
        int sk_t0, sk_t1, sk_p0, sk_p1;

        if (pole) {
            int r0 = (ty8 == 0) ? 0 : 25;
            int r1 = (ty8 == 0) ? 6 : 31;
            if (tid == 0) {
                sm.it.rowsrc[0] = g_binstart[cb][r0 * NBP];
                sm.it.rowoff[0] = g_binstart[cb][(r1 + 1) * NBP];
            }
            __syncthreads();
            int s0 = sm.it.rowsrc[0], e0 = sm.it.rowoff[0];
            ncand = e0 - s0;
            if (ncand <= CAP) {
                for (int i = tid; i < ncand; i += 256) {
                    float4 p = g_sorted[cb][s0 + i];
                    p.w = __uint_as_float((unsigned)(s0 + i));
                    sm.it.cand[i] = p;
                }
            }
            margin = (ty8 == 0) ? (7.0f * H_BIN - gth) : (gth - 25.0f * H_BIN);
            sk_t0 = r0; sk_t1 = r1; sk_p0 = 0; sk_p1 = NBP - 1;
        } else {
            int ht0 = max(bt0 - 2, 0), ht1 = min(bt0 + 5, NBT - 1);
            int hp0 = max(bp0 - 2, 0), hp1 = min(bp0 + 5, NBP - 1);
            int nrows = ht1 - ht0 + 1;
            if (tid < nrows) {
                int s = g_binstart[cb][(ht0 + tid) * NBP + hp0];
                int e = g_binstart[cb][(ht0 + tid) * NBP + hp1 + 1];
                sm.it.rowsrc[tid] = s;
                sm.it.rowoff[tid] = e - s;
            }
            __syncthreads();
            if (tid == 0) {
                int off = 0;
                for (int r = 0; r < nrows; ++r) {
                    int len = sm.it.rowoff[r];
                    sm.it.rowoff[r] = off;
                    off += len;
                }
                sm.it.rowoff[nrows] = off;
            }
            __syncthreads();
            ncand = sm.it.rowoff[nrows];
            if (ncand <= CAP) {
                for (int r = 0; r < nrows; ++r) {
                    int o0 = sm.it.rowoff[r], len = sm.it.rowoff[r + 1] - o0, s0 = sm.it.rowsrc[r];
                    for (int i = tid; i < len; i += 256) {
                        float4 p = g_sorted[cb][s0 + i];
                        p.w = __uint_as_float((unsigned)(s0 + i));
                        sm.it.cand[o0 + i] = p;
                    }
                }
            }
            float mT = (ht0 > 0)       ? (gth - (float)ht0 * H_BIN)       : 1e9f;
            float mB = (ht1 < NBT - 1) ? ((float)(ht1 + 1) * H_BIN - gth) : 1e9f;
            float gpp = gph + PI_F;
            float mL = (hp0 > 0)       ? (gpp - (float)hp0 * H_BIN)       : 1e9f;
            float mR = (hp1 < NBP - 1) ? ((float)(hp1 + 1) * H_BIN - gpp) : 1e9f;
            margin = fminf(fminf(mT, mB), fminf(mL, mR));
            sk_t0 = ht0; sk_t1 = ht1; sk_p0 = hp0; sk_p1 = hp1;
        }
        __syncthreads();

        bool ovf = ncand > CAP;
        unsigned k0 = KINF, k1 = KINF, k2 = KINF;

        if (!ovf) {
#pragma unroll 4
            for (int i = 0; i < ncand; ++i) {
                float4 p = sm.it.cand[i];
                float dx = gth - p.x, dy = gph - p.y;
                float d = fmaf(dx, dx, dy * dy);
                unsigned key = (__float_as_uint(d) & 0xFFFFF800u) | __float_as_uint(p.w);
                ins3(k0, k1, k2, key);
            }
        }

        float d2k = __uint_as_float(k2 & 0xFFFFF800u);
        if (ovf || d2k > margin * margin) {
            int bt = min(irow >> 2, NBT - 1);
            int bp = min(icol >> 2, NBP - 1);
            int st0 = ovf ? 1000 : sk_t0, st1 = ovf ? -1 : sk_t1;
            int sp0 = ovf ? 1000 : sk_p0, sp1 = ovf ? -1 : sk_p1;
            for (int R = 0; R <= 64; ++R) {
                if (R > 0) {
                    float lb = (float)(R - 1) * H_BIN;
                    d2k = __uint_as_float(k2 & 0xFFFFF800u);
                    if (d2k <= lb * lb) break;
                }
                int t0 = max(bt - R, 0), t1 = min(bt + R, NBT - 1);
                int p0 = max(bp - R, 0), p1 = min(bp + R, NBP - 1);
                for (int y = t0; y <= t1; ++y) {
                    bool full = (R == 0) || (y == bt - R) || (y == bt + R);
                    int xs = full ? p0 : (bp - R);
                    int xe = full ? p1 : (bp + R);
                    int xstep = full ? 1 : (2 * R);
                    for (int x = xs; x <= xe; x += xstep) {
                        if (x < 0 || x > NBP - 1) continue;
                        if (y >= st0 && y <= st1 && x >= sp0 && x <= sp1) continue;
                        int bi = y * NBP + x;
                        int s0 = g_binstart[cb][bi], s1 = g_binstart[cb][bi + 1];
                        for (int i = s0; i < s1; ++i) {
                            float4 p = g_sorted[cb][i];
                            float dx = gth - p.x, dy = gph - p.y;
                            float d = fmaf(dx, dx, dy * dy);
                            unsigned key = (__float_as_uint(d) & 0xFFFFF800u) | (unsigned)i;
                            ins3(k0, k1, k2, key);
                        }
                    }
                }
            }
        }

        float4 q0 = g_sorted[cb][k0 & 0x7FFu];
        float4 q1 = g_sorted[cb][k1 & 0x7FFu];
        float4 q2 = g_sorted[cb][k2 & 0x7FFu];
        float dx, dy;
        dx = gth - q0.x; dy = gph - q0.y; float e0 = fmaf(dx, dx, dy * dy);
        dx = gth - q1.x; dy = gph - q1.y; float e1 = fmaf(dx, dx, dy * dy);
        dx = gth - q2.x; dy = gph - q2.y; float e2 = fmaf(dx, dx, dy * dy);
        float s = e0 + e1 + e2;
        g_grid[cb][irow * NLON + icol] = (e0 * q0.z + e1 * q1.z + e2 * q2.z) / s;
    }
    gbar(1);

    // ================= Phase CD: DFT + Legendre + partial loss ==============
    // block = (batch b, mode m): 100 blocks; coalesced lane-over-n access.
    if (bid < NB * MMAX) {
        int b = bid / MMAX;
        int m = bid % MMAX;
        sm.cd.ctab[tid] = cosf((2.0f * PI_F / NLON) * (float)m * (float)tid);
        __syncthreads();

        // xf[k]: warp owns k = wid, wid+8, ...; lanes split n (coalesced LDG)
        for (int k = wid; k < NLAT; k += 8) {
            const float* gp = &g_grid[b][k * NLON];
            const float* gt = &g_grid[2 + b][k * NLON];
            float ap = 0.0f, at = 0.0f;
#pragma unroll
            for (int j = 0; j < 8; ++j) {
                int n = lane + 32 * j;
                float c = sm.cd.ctab[n];
                ap = fmaf(gp[n], c, ap);
                at = fmaf(gt[n], c, at);
            }
#pragma unroll
            for (int o = 16; o > 0; o >>= 1) {
                ap += __shfl_down_sync(0xffffffffu, ap, o);
                at += __shfl_down_sync(0xffffffffu, at, o);
            }
            if (lane == 0) {
                sm.cd.xfp[k] = ap * (2.0f * PI_F / NLON);
                sm.cd.xft[k] = at * (2.0f * PI_F / NLON);
            }
        }
        __syncthreads();

        // legendre contraction: thread = (l, quarter)
        {
            int l = tid & 63, q = tid >> 6;
            if (l < LMAX) {
                const float* pw = &g_pctw[m][l][q * 32];
                const float* xp = &sm.cd.xfp[q * 32];
                const float* xt = &sm.cd.xft[q * 32];
                float pc = 0.0f, tc = 0.0f;
#pragma unroll 8
                for (int k = 0; k < 32; ++k) {
                    float w = pw[k];
                    pc = fmaf(xp[k], w, pc);
                    tc = fmaf(xt[k], w, tc);
                }
                sm.cd.plp[q][l] = pc;
                sm.cd.plt[q][l] = tc;
            }
        }
        __syncthreads();
        if (tid < LMAX) {
            int l = tid;
            float pc = (sm.cd.plp[0][l] + sm.cd.plp[1][l]) + (sm.cd.plp[2][l] + sm.cd.plp[3][l]);
            float tc = (sm.cd.plt[0][l] + sm.cd.plt[1][l]) + (sm.cd.plt[2][l] + sm.cd.plt[3][l]);
            float d = pc - tc;
            float q = (float)(LMAX - 1 - l);
            g_part[b * (LMAX * MMAX) + l * MMAX + m] = d * d * expf(-q * q / (2.0f * LMAX * LMAX));
        }
    }

    // ================= Final: last block reduces ============================
    __syncthreads();
    if (tid == 0) {
        __threadfence();
        int t = atomicAdd(&g_done, 1);
        s_last = (t == NBLK - 1) ? 1 : 0;
    }
    __syncthreads();
    if (s_last) {
        __threadfence();
        float acc = 0.0f;
        for (int i = tid; i < NB * LMAX * MMAX; i += 256) acc += g_part[i];
#pragma unroll
        for (int o = 16; o > 0; o >>= 1) acc += __shfl_down_sync(0xffffffffu, acc, o);
        if (lane == 0) sm.red[wid] = acc;
        __syncthreads();
        if (tid == 0) {
            float v = 0.0f;
            for (int j = 0; j < 8; ++j) v += sm.red[j];
            out[0] = v / (float)NB;
            g_done = 0;
            __threadfence();
        }
    }
}

extern "C" void kernel_launch(void* const* d_in, const int* in_sizes, int n_in,
                              void* d_out, int out_size) {
    const float* pred = (const float*)d_in[0];
    const float* tgt  = (const float*)d_in[1];
    k_mega<<<NBLK, 256>>>(pred, tgt, (float*)d_out);
}

// round 11
// speedup vs baseline: 1.6692x; 1.6292x over previous
#include <cuda_runtime.h>
#include <math.h>

#define NLAT 128
#define NLON 256
#define LMAX 50
#define MMAX 50
#define NPTS 2048
#define NB   2
#define MG   (NLAT*NLON)
#define NBT  32
#define NBP  64
#define NBINS (NBT*NBP)
#define PI_F 3.14159265358979323846f
#define H_BIN (PI_F/32.0f)
#define INVH  (32.0f/PI_F)
#define CAP   1536
#define NBLK  512
#define KINF  0x7F7FFFFFu

// ---- device scratch (globals; zero-init at load) ----
__device__ float4 g_sorted[4][NPTS];
__device__ int    g_binstart[4][NBINS + 1];
__device__ float  g_grid[4][MG];
__device__ float  g_pctw[MMAX][LMAX][NLAT];
__device__ float  g_rexf[4][MMAX][NLAT];
__device__ float  g_part[NB * LMAX * MMAX];   // l<m entries stay 0 forever
__device__ int    g_barc[3 * 32];
__device__ int    g_done;

union Smem {
    struct { float4 pts[NPTS]; int cnt[NBINS]; int wsum[8]; } prep;   // ~41KB
    struct { float4 cand[CAP]; int rowoff[12]; int rowsrc[12]; } it;  // ~24KB
    struct { float row[NLON]; } rx;
    float red[64];
};

__device__ __forceinline__ void gbar(int id) {
    __syncthreads();
    if (threadIdx.x == 0) {
        __threadfence();
        atomicAdd(&g_barc[id * 32], 1);
        while (*(volatile int*)&g_barc[id * 32] < NBLK) __nanosleep(64);
        __threadfence();
        int l = atomicAdd(&g_barc[id * 32 + 1], 1);
        if (l == NBLK - 1) {
            *(volatile int*)&g_barc[id * 32]     = 0;
            *(volatile int*)&g_barc[id * 32 + 1] = 0;
            __threadfence();
        }
    }
    __syncthreads();
}

__device__ __forceinline__ int bin_of(float th, float ph) {
    int bt = (int)(th * INVH);
    int bp = (int)((ph + PI_F) * INVH);
    bt = min(max(bt, 0), NBT - 1);
    bp = min(max(bp, 0), NBP - 1);
    return bt * NBP + bp;
}

__device__ __forceinline__ void ins3(unsigned& k0, unsigned& k1, unsigned& k2, unsigned key) {
    unsigned t  = max(k0, key); k0 = min(k0, key);
    unsigned t2 = max(k1, t);   k1 = min(k1, t);
    k2 = min(k2, t2);
}

__global__ void __launch_bounds__(256, 4)
k_mega(const float* __restrict__ pred, const float* __restrict__ tgt,
       float* __restrict__ out) {
    __shared__ Smem sm;
    __shared__ int s_last;
    int bid  = blockIdx.x;
    int tid  = threadIdx.x;
    int lane = tid & 31;
    int wid  = tid >> 5;

    // ================= Phase A: prep (blocks 0-3) + pctw (4-28) =============
    if (bid < 4) {
        int cb = bid;
        int t = cb >> 1, b = cb & 1;
        const float* src = (t ? tgt : pred) + (size_t)b * NPTS * 3;
        for (int i = tid; i < NBINS; i += 256) sm.prep.cnt[i] = 0;
        __syncthreads();
        for (int i = tid; i < NPTS; i += 256) {
            float x = src[3 * i], y = src[3 * i + 1], z = src[3 * i + 2];
            float r   = sqrtf(x * x + y * y + z * z);
            float pn1 = sqrtf(y * y + z * z);
            float th  = acosf(fminf(fmaxf(x / r,   -1.0f), 1.0f));
            float a   = acosf(fminf(fmaxf(y / pn1, -1.0f), 1.0f));
            float ph  = ((z < 0.0f) ? (2.0f * PI_F - a) : a) - PI_F;
            float4 o; o.x = th; o.y = ph; o.z = r; o.w = 0.0f;
            sm.prep.pts[i] = o;
            atomicAdd(&sm.prep.cnt[bin_of(th, ph)], 1);
        }
        __syncthreads();
        int base = tid * 8;
        int local[8]; int s = 0;
#pragma unroll
        for (int j = 0; j < 8; ++j) { local[j] = s; s += sm.prep.cnt[base + j]; }
        int v = s;
#pragma unroll
        for (int o = 1; o < 32; o <<= 1) {
            int u = __shfl_up_sync(0xffffffffu, v, o);
            if (lane >= o) v += u;
        }
        if (lane == 31) sm.prep.wsum[wid] = v;
        __syncthreads();
        if (tid == 0) {
            int a = 0;
            for (int j = 0; j < 8; ++j) { int x = sm.prep.wsum[j]; sm.prep.wsum[j] = a; a += x; }
        }
        __syncthreads();
        int excl = v - s + sm.prep.wsum[wid];
#pragma unroll
        for (int j = 0; j < 8; ++j) {
            int off = excl + local[j];
            sm.prep.cnt[base + j] = off;
            g_binstart[cb][base + j] = off;
        }
        if (tid == 0) g_binstart[cb][NBINS] = NPTS;
        __syncthreads();
        for (int i = tid; i < NPTS; i += 256) {
            float4 p = sm.prep.pts[i];
            int pos = atomicAdd(&sm.prep.cnt[bin_of(p.x, p.y)], 1);
            g_sorted[cb][pos] = p;
        }
    } else if (bid < 29) {
        int m = (bid - 4) * 2 + (tid >> 7);
        int k = tid & 127;
        if (m < MMAX) {
            float theta = PI_F * (float)k / (float)(NLAT - 1);
            float cost  = cosf(theta);
            float sint  = sqrtf(fmaxf(1.0f - cost * cost, 0.0f));
            float c2  = cosf(2.0f * theta);
            float tc2 = 2.0f * c2;
            float cm1 = 1.0f, cj = c2;
            float v = 0.0f;
#pragma unroll 7
            for (int j = 1; j <= 63; ++j) {
                v = fmaf(cj, 2.0f / (4.0f * (float)j * (float)j - 1.0f), v);
                float cn = fmaf(tc2, cj, -cm1);
                cm1 = cj; cj = cn;
            }
            float w = (2.0f / 127.0f) * (1.0f - v);
            if (k == 0 || k == 127) w *= 0.5f;
            float pmm = sqrtf(1.0f / (4.0f * PI_F));
            for (int mm = 1; mm <= m; ++mm)
                pmm = -pmm * sqrtf((2.0f * mm + 1.0f) / (2.0f * mm)) * sint;
            for (int l = 0; l < m; ++l) g_pctw[m][l][k] = 0.0f;
            g_pctw[m][m][k] = pmm * w;
            if (m + 1 < LMAX) {
                float plm2 = pmm;
                float plm1 = sqrtf(2.0f * m + 3.0f) * cost * pmm;
                g_pctw[m][m + 1][k] = plm1 * w;
                for (int l = m + 2; l < LMAX; ++l) {
                    float fl = (float)l, fm = (float)m;
                    float a = sqrtf((4.0f * fl * fl - 1.0f) / (fl * fl - fm * fm));
                    float bq = sqrtf(((2.0f * fl + 1.0f) * (fl - 1.0f + fm) * (fl - 1.0f - fm)) /
                                     ((2.0f * fl - 3.0f) * (fl * fl - fm * fm)));
                    float pl = a * cost * plm1 - bq * plm2;
                    g_pctw[m][l][k] = pl * w;
                    plm2 = plm1; plm1 = pl;
                }
            }
        }
    }
    gbar(0);

    // ================= Phase B: 3-NN interp (512 tiles) =====================
    {
        int cb  = bid >> 7;
        int rem = bid & 127;
        int ty8 = rem >> 4, tx16 = rem & 15;
        int bt0 = ty8 * 4, bp0 = tx16 * 4;
        bool pole = (ty8 == 0) || (ty8 == 7);

        int irow = ty8 * 16 + (tid >> 4);
        int icol = tx16 * 16 + (tid & 15);
        float gth = (float)irow * (PI_F / NLAT);
        float gph = (float)(icol - NLAT) * (PI_F / NLAT);

        int ncand;
        float margin;
        int sk_t0, sk_t1, sk_p0, sk_p1;

        if (pole) {
            int r0 = (ty8 == 0) ? 0 : 25;
            int r1 = (ty8 == 0) ? 6 : 31;
            if (tid == 0) {
                sm.it.rowsrc[0] = g_binstart[cb][r0 * NBP];
                sm.it.rowoff[0] = g_binstart[cb][(r1 + 1) * NBP];
            }
            __syncthreads();
            int s0 = sm.it.rowsrc[0], e0 = sm.it.rowoff[0];
            ncand = e0 - s0;
            if (ncand <= CAP) {
                for (int i = tid; i < ncand; i += 256) {
                    float4 p = g_sorted[cb][s0 + i];
                    p.w = __uint_as_float((unsigned)(s0 + i));
                    sm.it.cand[i] = p;
                }
            }
            margin = (ty8 == 0) ? (7.0f * H_BIN - gth) : (gth - 25.0f * H_BIN);
            sk_t0 = r0; sk_t1 = r1; sk_p0 = 0; sk_p1 = NBP - 1;
        } else {
            int ht0 = max(bt0 - 2, 0), ht1 = min(bt0 + 5, NBT - 1);
            int hp0 = max(bp0 - 2, 0), hp1 = min(bp0 + 5, NBP - 1);
            int nrows = ht1 - ht0 + 1;
            if (tid < nrows) {
                int s = g_binstart[cb][(ht0 + tid) * NBP + hp0];
                int e = g_binstart[cb][(ht0 + tid) * NBP + hp1 + 1];
                sm.it.rowsrc[tid] = s;
                sm.it.rowoff[tid] = e - s;
            }
            __syncthreads();
            if (tid == 0) {
                int off = 0;
                for (int r = 0; r < nrows; ++r) {
                    int len = sm.it.rowoff[r];
                    sm.it.rowoff[r] = off;
                    off += len;
                }
                sm.it.rowoff[nrows] = off;
            }
            __syncthreads();
            ncand = sm.it.rowoff[nrows];
            if (ncand <= CAP) {
                for (int r = 0; r < nrows; ++r) {
                    int o0 = sm.it.rowoff[r], len = sm.it.rowoff[r + 1] - o0, s0 = sm.it.rowsrc[r];
                    for (int i = tid; i < len; i += 256) {
                        float4 p = g_sorted[cb][s0 + i];
                        p.w = __uint_as_float((unsigned)(s0 + i));
                        sm.it.cand[o0 + i] = p;
                    }
                }
            }
            float mT = (ht0 > 0)       ? (gth - (float)ht0 * H_BIN)       : 1e9f;
            float mB = (ht1 < NBT - 1) ? ((float)(ht1 + 1) * H_BIN - gth) : 1e9f;
            float gpp = gph + PI_F;
            float mL = (hp0 > 0)       ? (gpp - (float)hp0 * H_BIN)       : 1e9f;
            float mR = (hp1 < NBP - 1) ? ((float)(hp1 + 1) * H_BIN - gpp) : 1e9f;
            margin = fminf(fminf(mT, mB), fminf(mL, mR));
            sk_t0 = ht0; sk_t1 = ht1; sk_p0 = hp0; sk_p1 = hp1;
        }
        __syncthreads();

        bool ovf = ncand > CAP;
        unsigned k0 = KINF, k1 = KINF, k2 = KINF;

        if (!ovf) {
#pragma unroll 4
            for (int i = 0; i < ncand; ++i) {
                float4 p = sm.it.cand[i];
                float dx = gth - p.x, dy = gph - p.y;
                float d = fmaf(dx, dx, dy * dy);
                unsigned key = (__float_as_uint(d) & 0xFFFFF800u) | __float_as_uint(p.w);
                ins3(k0, k1, k2, key);
            }
        }

        float d2k = __uint_as_float(k2 & 0xFFFFF800u);
        if (ovf || d2k > margin * margin) {
            int bt = min(irow >> 2, NBT - 1);
            int bp = min(icol >> 2, NBP - 1);
            int st0 = ovf ? 1000 : sk_t0, st1 = ovf ? -1 : sk_t1;
            int sp0 = ovf ? 1000 : sk_p0, sp1 = ovf ? -1 : sk_p1;
            for (int R = 0; R <= 64; ++R) {
                if (R > 0) {
                    float lb = (float)(R - 1) * H_BIN;
                    d2k = __uint_as_float(k2 & 0xFFFFF800u);
                    if (d2k <= lb * lb) break;
                }
                int t0 = max(bt - R, 0), t1 = min(bt + R, NBT - 1);
                int p0 = max(bp - R, 0), p1 = min(bp + R, NBP - 1);
                for (int y = t0; y <= t1; ++y) {
                    bool full = (R == 0) || (y == bt - R) || (y == bt + R);
                    int xs = full ? p0 : (bp - R);
                    int xe = full ? p1 : (bp + R);
                    int xstep = full ? 1 : (2 * R);
                    for (int x = xs; x <= xe; x += xstep) {
                        if (x < 0 || x > NBP - 1) continue;
                        if (y >= st0 && y <= st1 && x >= sp0 && x <= sp1) continue;
                        int bi = y * NBP + x;
                        int s0 = g_binstart[cb][bi], s1 = g_binstart[cb][bi + 1];
                        for (int i = s0; i < s1; ++i) {
                            float4 p = g_sorted[cb][i];
                            float dx = gth - p.x, dy = gph - p.y;
                            float d = fmaf(dx, dx, dy * dy);
                            unsigned key = (__float_as_uint(d) & 0xFFFFF800u) | (unsigned)i;
                            ins3(k0, k1, k2, key);
                        }
                    }
                }
            }
        }

        float4 q0 = g_sorted[cb][k0 & 0x7FFu];
        float4 q1 = g_sorted[cb][k1 & 0x7FFu];
        float4 q2 = g_sorted[cb][k2 & 0x7FFu];
        float dx, dy;
        dx = gth - q0.x; dy = gph - q0.y; float e0 = fmaf(dx, dx, dy * dy);
        dx = gth - q1.x; dy = gph - q1.y; float e1 = fmaf(dx, dx, dy * dy);
        dx = gth - q2.x; dy = gph - q2.y; float e2 = fmaf(dx, dx, dy * dy);
        float s = e0 + e1 + e2;
        g_grid[cb][irow * NLON + icol] = (e0 * q0.z + e1 * q1.z + e2 * q2.z) / s;
    }
    gbar(1);

    // ================= Phase C: DFT real part (block = grid row) ============
    // thread = (m = tid>>2, quarter q = tid&3); stride-2 Chebyshev recurrence.
    {
        int combo = bid >> 7;
        int k     = bid & 127;
        sm.rx.row[tid] = g_grid[combo][k * NLON + tid];
        __syncthreads();
        int m = tid >> 2, q = tid & 3;
        float am = (2.0f * PI_F / NLON) * (float)m;
        int n0 = q * 64;
        float cE  = cosf(am * (float)n0);
        float cE2 = cosf(am * (float)(n0 + 2));
        float cO  = cosf(am * (float)(n0 + 1));
        float cO2 = cosf(am * (float)(n0 + 3));
        float stp = 2.0f * cosf(2.0f * am);
        const float* rw = &sm.rx.row[n0];
        float accE = 0.0f, accO = 0.0f;
#pragma unroll 8
        for (int i = 0; i < 32; ++i) {
            accE = fmaf(rw[2 * i],     cE, accE);
            accO = fmaf(rw[2 * i + 1], cO, accO);
            float nE = fmaf(stp, cE2, -cE); cE = cE2; cE2 = nE;
            float nO = fmaf(stp, cO2, -cO); cO = cO2; cO2 = nO;
        }
        float acc = accE + accO;
        acc += __shfl_xor_sync(0xffffffffu, acc, 1);
        acc += __shfl_xor_sync(0xffffffffu, acc, 2);
        if (m < MMAX && q == 0)
            g_rexf[combo][m][k] = acc * (2.0f * PI_F / NLON);
    }
    gbar(2);

    // ================= Phase D: coefficients + partial loss (l >= m only) ===
    {
        int gw0 = bid * 8 + wid;
        for (int task = gw0; task < NB * LMAX * MMAX; task += 4096) {
            int b = task / (LMAX * MMAX);
            int r = task % (LMAX * MMAX);
            int l = r / MMAX;
            int m = r % MMAX;
            if (l < m) continue;      // pctw==0 there; g_part stays 0 (zero-init)
            const float* pw = g_pctw[m][l];
            const float* xp = g_rexf[b][m];
            const float* xt = g_rexf[2 + b][m];
            float pc = 0.0f, tc = 0.0f;
#pragma unroll
            for (int k = lane; k < NLAT; k += 32) {
                float w = pw[k];
                pc = fmaf(xp[k], w, pc);
                tc = fmaf(xt[k], w, tc);
            }
#pragma unroll
            for (int o = 16; o > 0; o >>= 1) {
                pc += __shfl_down_sync(0xffffffffu, pc, o);
                tc += __shfl_down_sync(0xffffffffu, tc, o);
            }
            if (lane == 0) {
                float d = pc - tc;
                float qd = (float)(LMAX - 1 - l);
                g_part[task] = d * d * expf(-qd * qd / (2.0f * LMAX * LMAX));
            }
        }
    }

    // ================= Final: last block reduces ============================
    __syncthreads();
    if (tid == 0) {
        __threadfence();
        int t = atomicAdd(&g_done, 1);
        s_last = (t == NBLK - 1) ? 1 : 0;
    }
    __syncthreads();
    if (s_last) {
        __threadfence();
        float acc = 0.0f;
        for (int i = tid; i < NB * LMAX * MMAX; i += 256) acc += g_part[i];
#pragma unroll
        for (int o = 16; o > 0; o >>= 1) acc += __shfl_down_sync(0xffffffffu, acc, o);
        if (lane == 0) sm.red[wid] = acc;
        __syncthreads();
        if (tid == 0) {
            float v = 0.0f;
            for (int j = 0; j < 8; ++j) v += sm.red[j];
            out[0] = v / (float)NB;
            g_done = 0;
            __threadfence();
        }
    }
}

extern "C" void kernel_launch(void* const* d_in, const int* in_sizes, int n_in,
                              void* d_out, int out_size) {
    const float* pred = (const float*)d_in[0];
    const float* tgt  = (const float*)d_in[1];
    k_mega<<<NBLK, 256>>>(pred, tgt, (float*)d_out);
}

// round 12
// speedup vs baseline: 1.7686x; 1.0595x over previous
#include <cuda_runtime.h>
#include <math.h>

#define NLAT 128
#define NLON 256
#define LMAX 50
#define MMAX 50
#define NPTS 2048
#define NB   2
#define MG   (NLAT*NLON)
#define NBT  32
#define NBP  64
#define NBINS (NBT*NBP)
#define PI_F 3.14159265358979323846f
#define H_BIN (PI_F/32.0f)
#define INVH  (32.0f/PI_F)
#define CAP   1536
#define NBLK  512
#define KINF  0x7F7FFFFFu
#define FIDX(n) ((n) + ((n) >> 5))

// ---- device scratch (globals; zero-init at load) ----
__device__ float4 g_sorted[4][NPTS];
__device__ int    g_binstart[4][NBINS + 1];
__device__ float  g_grid[4][MG];
__device__ float  g_pctw[MMAX][LMAX][NLAT];
__device__ float  g_rexf[4][MMAX][NLAT];
__device__ float  g_part[NB * LMAX * MMAX];   // l<m entries stay 0 forever
__device__ int    g_barc[3 * 32];
__device__ int    g_done;

union Smem {
    struct { float4 pts[NPTS]; int cnt[NBINS]; int wsum[8]; } prep;   // ~41KB
    struct { float4 cand[CAP]; int rowoff[12]; int rowsrc[12]; } it;  // ~24KB
    struct { float row[NLON]; float fold[136]; } rx;
    float red[64];
};

__device__ __forceinline__ void gbar(int id) {
    __syncthreads();
    if (threadIdx.x == 0) {
        __threadfence();
        atomicAdd(&g_barc[id * 32], 1);
        while (*(volatile int*)&g_barc[id * 32] < NBLK) __nanosleep(64);
        __threadfence();
        int l = atomicAdd(&g_barc[id * 32 + 1], 1);
        if (l == NBLK - 1) {
            *(volatile int*)&g_barc[id * 32]     = 0;
            *(volatile int*)&g_barc[id * 32 + 1] = 0;
            __threadfence();
        }
    }
    __syncthreads();
}

__device__ __forceinline__ int bin_of(float th, float ph) {
    int bt = (int)(th * INVH);
    int bp = (int)((ph + PI_F) * INVH);
    bt = min(max(bt, 0), NBT - 1);
    bp = min(max(bp, 0), NBP - 1);
    return bt * NBP + bp;
}

__device__ __forceinline__ void ins3(unsigned& k0, unsigned& k1, unsigned& k2, unsigned key) {
    unsigned t  = max(k0, key); k0 = min(k0, key);
    unsigned t2 = max(k1, t);   k1 = min(k1, t);
    k2 = min(k2, t2);
}

__global__ void __launch_bounds__(256, 4)
k_mega(const float* __restrict__ pred, const float* __restrict__ tgt,
       float* __restrict__ out) {
    __shared__ Smem sm;
    __shared__ int s_last;
    int bid  = blockIdx.x;
    int tid  = threadIdx.x;
    int lane = tid & 31;
    int wid  = tid >> 5;

    // ================= Phase A: prep (blocks 0-3) + pctw (4-28) =============
    if (bid < 4) {
        int cb = bid;
        int t = cb >> 1, b = cb & 1;
        const float* src = (t ? tgt : pred) + (size_t)b * NPTS * 3;
        for (int i = tid; i < NBINS; i += 256) sm.prep.cnt[i] = 0;
        __syncthreads();
        for (int i = tid; i < NPTS; i += 256) {
            float x = src[3 * i], y = src[3 * i + 1], z = src[3 * i + 2];
            float r   = sqrtf(x * x + y * y + z * z);
            float pn1 = sqrtf(y * y + z * z);
            float th  = acosf(fminf(fmaxf(x / r,   -1.0f), 1.0f));
            float a   = acosf(fminf(fmaxf(y / pn1, -1.0f), 1.0f));
            float ph  = ((z < 0.0f) ? (2.0f * PI_F - a) : a) - PI_F;
            float4 o; o.x = th; o.y = ph; o.z = r; o.w = 0.0f;
            sm.prep.pts[i] = o;
            atomicAdd(&sm.prep.cnt[bin_of(th, ph)], 1);
        }
        __syncthreads();
        int base = tid * 8;
        int local[8]; int s = 0;
#pragma unroll
        for (int j = 0; j < 8; ++j) { local[j] = s; s += sm.prep.cnt[base + j]; }
        int v = s;
#pragma unroll
        for (int o = 1; o < 32; o <<= 1) {
            int u = __shfl_up_sync(0xffffffffu, v, o);
            if (lane >= o) v += u;
        }
        if (lane == 31) sm.prep.wsum[wid] = v;
        __syncthreads();
        if (tid == 0) {
            int a = 0;
            for (int j = 0; j < 8; ++j) { int x = sm.prep.wsum[j]; sm.prep.wsum[j] = a; a += x; }
        }
        __syncthreads();
        int excl = v - s + sm.prep.wsum[wid];
#pragma unroll
        for (int j = 0; j < 8; ++j) {
            int off = excl + local[j];
            sm.prep.cnt[base + j] = off;
            g_binstart[cb][base + j] = off;
        }
        if (tid == 0) g_binstart[cb][NBINS] = NPTS;
        __syncthreads();
        for (int i = tid; i < NPTS; i += 256) {
            float4 p = sm.prep.pts[i];
            int pos = atomicAdd(&sm.prep.cnt[bin_of(p.x, p.y)], 1);
            g_sorted[cb][pos] = p;
        }
    } else if (bid < 29) {
        int m = (bid - 4) * 2 + (tid >> 7);
        int k = tid & 127;
        if (m < MMAX) {
            float theta = PI_F * (float)k / (float)(NLAT - 1);
            float cost  = cosf(theta);
            float sint  = sqrtf(fmaxf(1.0f - cost * cost, 0.0f));
            float c2  = cosf(2.0f * theta);
            float tc2 = 2.0f * c2;
            float cm1 = 1.0f, cj = c2;
            float v = 0.0f;
#pragma unroll 7
            for (int j = 1; j <= 63; ++j) {
                v = fmaf(cj, 2.0f / (4.0f * (float)j * (float)j - 1.0f), v);
                float cn = fmaf(tc2, cj, -cm1);
                cm1 = cj; cj = cn;
            }
            float w = (2.0f / 127.0f) * (1.0f - v);
            if (k == 0 || k == 127) w *= 0.5f;
            float pmm = sqrtf(1.0f / (4.0f * PI_F));
            for (int mm = 1; mm <= m; ++mm)
                pmm = -pmm * sqrtf((2.0f * mm + 1.0f) / (2.0f * mm)) * sint;
            for (int l = 0; l < m; ++l) g_pctw[m][l][k] = 0.0f;
            g_pctw[m][m][k] = pmm * w;
            if (m + 1 < LMAX) {
                float plm2 = pmm;
                float plm1 = sqrtf(2.0f * m + 3.0f) * cost * pmm;
                g_pctw[m][m + 1][k] = plm1 * w;
                for (int l = m + 2; l < LMAX; ++l) {
                    float fl = (float)l, fm = (float)m;
                    float a = sqrtf((4.0f * fl * fl - 1.0f) / (fl * fl - fm * fm));
                    float bq = sqrtf(((2.0f * fl + 1.0f) * (fl - 1.0f + fm) * (fl - 1.0f - fm)) /
                                     ((2.0f * fl - 3.0f) * (fl * fl - fm * fm)));
                    float pl = a * cost * plm1 - bq * plm2;
                    g_pctw[m][l][k] = pl * w;
                    plm2 = plm1; plm1 = pl;
                }
            }
        }
    }
    gbar(0);

    // ================= Phase B: 3-NN interp (512 tiles, unified halo) =======
    {
        int cb  = bid >> 7;
        int rem = bid & 127;
        int ty8 = rem >> 4, tx16 = rem & 15;
        int bt0 = ty8 * 4, bp0 = tx16 * 4;
        bool pole = (ty8 == 0) || (ty8 == 7);

        int irow = ty8 * 16 + (tid >> 4);
        int icol = tx16 * 16 + (tid & 15);
        float gth = (float)irow * (PI_F / NLAT);
        float gph = (float)(icol - NLAT) * (PI_F / NLAT);

        int ht0, ht1, hp0, hp1;
        if (pole) {
            ht0 = (ty8 == 0) ? 0 : 25;
            ht1 = (ty8 == 0) ? 6 : 31;
            hp0 = max(bp0 - 8, 0);
            hp1 = min(bp0 + 11, NBP - 1);
        } else {
            ht0 = max(bt0 - 2, 0); ht1 = min(bt0 + 5, NBT - 1);
            hp0 = max(bp0 - 2, 0); hp1 = min(bp0 + 5, NBP - 1);
        }
        int nrows = ht1 - ht0 + 1;
        if (tid < nrows) {
            int s = g_binstart[cb][(ht0 + tid) * NBP + hp0];
            int e = g_binstart[cb][(ht0 + tid) * NBP + hp1 + 1];
            sm.it.rowsrc[tid] = s;
            sm.it.rowoff[tid] = e - s;
        }
        __syncthreads();
        if (tid == 0) {
            int off = 0;
            for (int r = 0; r < nrows; ++r) {
                int len = sm.it.rowoff[r];
                sm.it.rowoff[r] = off;
                off += len;
            }
            sm.it.rowoff[nrows] = off;
        }
        __syncthreads();
        int ncand = sm.it.rowoff[nrows];
        if (ncand <= CAP) {
            for (int r = 0; r < nrows; ++r) {
                int o0 = sm.it.rowoff[r], len = sm.it.rowoff[r + 1] - o0, s0 = sm.it.rowsrc[r];
                for (int i = tid; i < len; i += 256) {
                    float4 p = g_sorted[cb][s0 + i];
                    p.w = __uint_as_float((unsigned)(s0 + i));
                    sm.it.cand[o0 + i] = p;
                }
            }
        }
        float mT = (ht0 > 0)       ? (gth - (float)ht0 * H_BIN)       : 1e9f;
        float mB = (ht1 < NBT - 1) ? ((float)(ht1 + 1) * H_BIN - gth) : 1e9f;
        float gpp = gph + PI_F;
        float mL = (hp0 > 0)       ? (gpp - (float)hp0 * H_BIN)       : 1e9f;
        float mR = (hp1 < NBP - 1) ? ((float)(hp1 + 1) * H_BIN - gpp) : 1e9f;
        float margin = fminf(fminf(mT, mB), fminf(mL, mR));
        __syncthreads();

        bool ovf = ncand > CAP;
        unsigned k0 = KINF, k1 = KINF, k2 = KINF;

        if (!ovf) {
#pragma unroll 4
            for (int i = 0; i < ncand; ++i) {
                float4 p = sm.it.cand[i];
                float dx = gth - p.x, dy = gph - p.y;
                float d = fmaf(dx, dx, dy * dy);
                unsigned key = (__float_as_uint(d) & 0xFFFFF800u) | __float_as_uint(p.w);
                ins3(k0, k1, k2, key);
            }
        }

        float d2k = __uint_as_float(k2 & 0xFFFFF800u);
        if (ovf || d2k > margin * margin) {
            int bt = min(irow >> 2, NBT - 1);
            int bp = min(icol >> 2, NBP - 1);
            int st0 = ovf ? 1000 : ht0, st1 = ovf ? -1 : ht1;
            int sp0 = ovf ? 1000 : hp0, sp1 = ovf ? -1 : hp1;
            for (int R = 0; R <= 64; ++R) {
                if (R > 0) {
                    float lb = (float)(R - 1) * H_BIN;
                    d2k = __uint_as_float(k2 & 0xFFFFF800u);
                    if (d2k <= lb * lb) break;
                }
                int t0 = max(bt - R, 0), t1 = min(bt + R, NBT - 1);
                int p0 = max(bp - R, 0), p1 = min(bp + R, NBP - 1);
                for (int y = t0; y <= t1; ++y) {
                    bool full = (R == 0) || (y == bt - R) || (y == bt + R);
                    int xs = full ? p0 : (bp - R);
                    int xe = full ? p1 : (bp + R);
                    int xstep = full ? 1 : (2 * R);
                    for (int x = xs; x <= xe; x += xstep) {
                        if (x < 0 || x > NBP - 1) continue;
                        if (y >= st0 && y <= st1 && x >= sp0 && x <= sp1) continue;
                        int bi = y * NBP + x;
                        int s0 = g_binstart[cb][bi], s1 = g_binstart[cb][bi + 1];
                        for (int i = s0; i < s1; ++i) {
                            float4 p = g_sorted[cb][i];
                            float dx = gth - p.x, dy = gph - p.y;
                            float d = fmaf(dx, dx, dy * dy);
                            unsigned key = (__float_as_uint(d) & 0xFFFFF800u) | (unsigned)i;
                            ins3(k0, k1, k2, key);
                        }
                    }
                }
            }
        }

        float4 q0 = g_sorted[cb][k0 & 0x7FFu];
        float4 q1 = g_sorted[cb][k1 & 0x7FFu];
        float4 q2 = g_sorted[cb][k2 & 0x7FFu];
        float dx, dy;
        dx = gth - q0.x; dy = gph - q0.y; float e0 = fmaf(dx, dx, dy * dy);
        dx = gth - q1.x; dy = gph - q1.y; float e1 = fmaf(dx, dx, dy * dy);
        dx = gth - q2.x; dy = gph - q2.y; float e2 = fmaf(dx, dx, dy * dy);
        float s = e0 + e1 + e2;
        g_grid[cb][irow * NLON + icol] = (e0 * q0.z + e1 * q1.z + e2 * q2.z) / s;
    }
    gbar(1);

    // ================= Phase C: DFT via fold + Chebyshev ====================
    // fold[n] = row[n] + row[256-n] (n=1..127), shared by all m of the block.
    {
        int combo = bid >> 7;
        int k     = bid & 127;
        sm.rx.row[tid] = g_grid[combo][k * NLON + tid];
        __syncthreads();
        if (tid == 0)            sm.rx.fold[FIDX(0)] = sm.rx.row[0];
        else if (tid < 128)      sm.rx.fold[FIDX(tid)] = sm.rx.row[tid] + sm.rx.row[256 - tid];
        __syncthreads();

        int m = tid >> 2, q = tid & 3;
        float am = (PI_F / 128.0f) * (float)m;
        int n0 = q * 32;
        float s0, c0, s1, c1;
        sincosf(am * (float)n0, &s0, &c0);
        sincosf(am, &s1, &c1);
        float c2 = fmaf(2.0f * c1, c1, -1.0f);
        float s2 = 2.0f * s1 * c1;
        float cE  = c0;
        float cE2 = c0 * c2 - s0 * s2;
        float cO  = c0 * c1 - s0 * s1;
        float sO  = s0 * c1 + c0 * s1;
        float cO2 = cO * c2 - sO * s2;
        float stp = 2.0f * c2;
        float accE = 0.0f, accO = 0.0f;
#pragma unroll
        for (int i = 0; i < 16; ++i) {
            accE = fmaf(sm.rx.fold[FIDX(n0 + 2 * i)],     cE, accE);
            accO = fmaf(sm.rx.fold[FIDX(n0 + 2 * i + 1)], cO, accO);
            float nE = fmaf(stp, cE2, -cE); cE = cE2; cE2 = nE;
            float nO = fmaf(stp, cO2, -cO); cO = cO2; cO2 = nO;
        }
        float acc = accE + accO;
        acc += __shfl_xor_sync(0xffffffffu, acc, 1);
        acc += __shfl_xor_sync(0xffffffffu, acc, 2);
        if (q == 0 && m < MMAX) {
            float last = sm.rx.row[128] * ((m & 1) ? -1.0f : 1.0f);
            g_rexf[combo][m][k] = (acc + last) * (2.0f * PI_F / NLON);
        }
    }
    gbar(2);

    // ================= Phase D: coefficients + partial loss (l >= m only) ===
    {
        int gw0 = bid * 8 + wid;
        for (int task = gw0; task < NB * LMAX * MMAX; task += 4096) {
            int b = task / (LMAX * MMAX);
            int r = task % (LMAX * MMAX);
            int l = r / MMAX;
            int m = r % MMAX;
            if (l < m) continue;
            const float* pw = g_pctw[m][l];
            const float* xp = g_rexf[b][m];
            const float* xt = g_rexf[2 + b][m];
            float pc = 0.0f, tc = 0.0f;
#pragma unroll
            for (int k = lane; k < NLAT; k += 32) {
                float w = pw[k];
                pc = fmaf(xp[k], w, pc);
                tc = fmaf(xt[k], w, tc);
            }
#pragma unroll
            for (int o = 16; o > 0; o >>= 1) {
                pc += __shfl_down_sync(0xffffffffu, pc, o);
                tc += __shfl_down_sync(0xffffffffu, tc, o);
            }
            if (lane == 0) {
                float d = pc - tc;
                float qd = (float)(LMAX - 1 - l);
                g_part[task] = d * d * expf(-qd * qd / (2.0f * LMAX * LMAX));
            }
        }
    }

    // ================= Final: last block reduces ============================
    __syncthreads();
    if (tid == 0) {
        __threadfence();
        int t = atomicAdd(&g_done, 1);
        s_last = (t == NBLK - 1) ? 1 : 0;
    }
    __syncthreads();
    if (s_last) {
        __threadfence();
        float acc = 0.0f;
        for (int i = tid; i < NB * LMAX * MMAX; i += 256) acc += g_part[i];
#pragma unroll
        for (int o = 16; o > 0; o >>= 1) acc += __shfl_down_sync(0xffffffffu, acc, o);
        if (lane == 0) sm.red[wid] = acc;
        __syncthreads();
        if (tid == 0) {
            float v = 0.0f;
            for (int j = 0; j < 8; ++j) v += sm.red[j];
            out[0] = v / (float)NB;
            g_done = 0;
            __threadfence();
        }
    }
}

extern "C" void kernel_launch(void* const* d_in, const int* in_sizes, int n_in,
                              void* d_out, int out_size) {
    const float* pred = (const float*)d_in[0];
    const float* tgt  = (const float*)d_in[1];
    k_mega<<<NBLK, 256>>>(pred, tgt, (float*)d_out);
}